// round 5
// baseline (speedup 1.0000x reference)
#include <cuda_runtime.h>
#include <math.h>
#include <stdint.h>

// Problem constants
#define Bb   8
#define Nn   2048
#define Mm   1024
#define BM   8192          // B*M
#define Kk   64
#define Ff   64
#define C0c  67
#define C1c  64
#define C2c  128

// Output layout (float32, concatenated reference outputs)
#define OFF_POS   1048576   // BM*C2
#define OFF_BATCH 1073152   // + BM*3
#define OFF_IDX   1081344   // + BM

// ---------------- device scratch (static, no allocation) ----------------
__device__ int   g_idxLoc[BM];
__device__ float g_qpos[BM * 3];
__device__ int   g_nbr[BM * Kk];
__device__ int   g_cnt[BM];
__device__ int   g_V;
__device__ float g_h1[BM * Kk * C1c];           // 128 MB (layer-1 activations)
__device__ float g_hmax[BM * C2c];              // masked max of h2 (pre-BN)
__device__ float g_hmin[BM * C2c];              // masked min of h2 (pre-BN)
__device__ float g_ps1[BM * C1c], g_pq1[BM * C1c];
__device__ float g_ps2[BM * C2c], g_pq2[BM * C2c];
__device__ float g_a1[C1c], g_o1[C1c], g_a2[C2c], g_o2[C2c];

// Strict (non-contracted) squared distance — must match XLA's fp32 mul/add
__device__ __forceinline__ float dist2s(float ax, float ay, float az,
                                        float bx, float by, float bz) {
    float dx = ax - bx, dy = ay - by, dz = az - bz;
    return __fadd_rn(__fadd_rn(__fmul_rn(dx, dx), __fmul_rn(dy, dy)),
                     __fmul_rn(dz, dz));
}

// ---------------- K1: farthest point sampling (1 block / batch) ----------------
// Triple-buffered shared argmax slot: iteration t writes slot t%3 (atomicMax),
// reads it after the barrier, and resets slot (t+2)%3 — whose last reads were
// two barrier-epochs ago and whose next write is one epoch later. Race-free
// with a single __syncthreads per iteration.
__global__ void __launch_bounds__(1024) k_fps(const float* __restrict__ pos) {
    const int b = blockIdx.x;
    const int tid = threadIdx.x;
    __shared__ float sx[Nn], sy[Nn], sz[Nn];
    __shared__ unsigned long long skey[3];

    const float* p = pos + (size_t)b * Nn * 3;
    for (int e = tid; e < Nn * 3; e += 1024) {
        float v = p[e];
        int i = e / 3, c = e - 3 * i;
        if (c == 0) sx[i] = v; else if (c == 1) sy[i] = v; else sz[i] = v;
    }
    if (tid < 3) skey[tid] = 0ull;
    __syncthreads();

    const int i0 = tid, i1 = tid + 1024;
    const float x0 = sx[i0], y0 = sy[i0], z0 = sz[i0];
    const float x1 = sx[i1], y1 = sy[i1], z1 = sz[i1];

    float cx = sx[0], cy = sy[0], cz = sz[0];
    float m0 = dist2s(x0, y0, z0, cx, cy, cz);
    float m1 = dist2s(x1, y1, z1, cx, cy, cz);

    if (tid == 0) {
        g_idxLoc[b * Mm] = 0;
        float* qp = g_qpos + (size_t)(b * Mm) * 3;
        qp[0] = cx; qp[1] = cy; qp[2] = cz;
    }
    const int lane = tid & 31;

    for (int t = 1; t < Mm; ++t) {
        // local best (ties -> lower index)
        float bv; int bi;
        if (m0 >= m1) { bv = m0; bi = i0; } else { bv = m1; bi = i1; }
        // pack: value bits (>=0 so monotone) high, (2048 - i) low -> max = first max
        unsigned long long key =
            ((unsigned long long)__float_as_uint(bv) << 32) |
            (unsigned int)(Nn - bi);
        #pragma unroll
        for (int s = 16; s; s >>= 1) {
            unsigned long long o = __shfl_xor_sync(0xffffffffu, key, s);
            key = (o > key) ? o : key;
        }
        const int slot = t % 3;
        if (lane == 0) atomicMax(&skey[slot], key);
        __syncthreads();
        unsigned long long best = skey[slot];
        if (tid == 0) skey[(t + 2) % 3] = 0ull;   // safe: read 2 epochs ago, written next epoch
        int nxt = Nn - (int)(unsigned int)(best & 0xffffffffu);
        cx = sx[nxt]; cy = sy[nxt]; cz = sz[nxt];
        if (tid == 0) {
            g_idxLoc[b * Mm + t] = nxt;
            float* qp = g_qpos + (size_t)(b * Mm + t) * 3;
            qp[0] = cx; qp[1] = cy; qp[2] = cz;
        }
        float d0 = dist2s(x0, y0, z0, cx, cy, cz);
        float d1 = dist2s(x1, y1, z1, cx, cy, cz);
        m0 = fminf(m0, d0);
        m1 = fminf(m1, d1);
    }
}

// ---------------- K2: ball query, first K in index order (1 warp / center) ----------------
__global__ void __launch_bounds__(256) k_ball(const float* __restrict__ pos) {
    int gw = (blockIdx.x * blockDim.x + threadIdx.x) >> 5;
    if (gw >= BM) return;
    const int lane = threadIdx.x & 31;
    const int b = gw >> 10;
    const float* p = pos + (size_t)b * Nn * 3;
    const float qx = g_qpos[gw * 3 + 0];
    const float qy = g_qpos[gw * 3 + 1];
    const float qz = g_qpos[gw * 3 + 2];
    int cnt = 0;
    for (int base = 0; base < Nn; base += 32) {
        int i = base + lane;
        float px = p[i * 3 + 0], py = p[i * 3 + 1], pz = p[i * 3 + 2];
        float d2 = dist2s(px, py, pz, qx, qy, qz);
        bool in = (d2 <= 0.04f);   // float32(R*R), same promotion as reference
        unsigned mask = __ballot_sync(0xffffffffu, in);
        int pre = __popc(mask & ((1u << lane) - 1u));
        int pp2 = cnt + pre;
        if (in && pp2 < Kk) g_nbr[gw * Kk + pp2] = i;
        cnt += __popc(mask);
        if (cnt >= Kk) break;
    }
    if (lane == 0) g_cnt[gw] = (cnt < Kk) ? cnt : Kk;
}

// ---------------- count total valid edges ----------------
__global__ void __launch_bounds__(256) k_count() {
    __shared__ int sr[256];
    int tid = threadIdx.x;
    int s = 0;
    for (int i = tid; i < BM; i += 256) s += g_cnt[i];
    sr[tid] = s; __syncthreads();
    for (int st = 128; st; st >>= 1) {
        if (tid < st) sr[tid] += sr[tid + st];
        __syncthreads();
    }
    if (tid == 0) g_V = sr[0];
}

// ---------------- K3: layer-1 (67->64) + partial BN1 stats ----------------
// block = one (b,m) center; 256 thr: c = tid&63 (channel), grp = tid>>6 (16 edges each)
#define FT_STRIDE 68
__global__ void __launch_bounds__(256) k_layer1(
    const float* __restrict__ x, const float* __restrict__ pos,
    const float* __restrict__ W1, const float* __restrict__ b1) {
    extern __shared__ float smem[];
    float* featT = smem;                        // [67][68]
    float* W1s   = featT + C0c * FT_STRIDE;     // [67][64]
    float* red   = W1s + C0c * C1c;             // [2][4][64]
    __shared__ int snbr[Kk];

    const int bm = blockIdx.x;
    const int b = bm >> 10;
    const int tid = threadIdx.x;
    const int cnt = g_cnt[bm];

    if (tid < Kk) snbr[tid] = (tid < cnt) ? g_nbr[bm * Kk + tid] : 0;
    for (int e = tid; e < C0c * C1c; e += 256) W1s[e] = W1[e];
    __syncthreads();

    const float* xb = x + (size_t)b * Nn * Ff;
    for (int e = tid; e < cnt * Ff; e += 256) {
        int k = e >> 6, j = e & 63;
        featT[j * FT_STRIDE + k] = xb[(size_t)snbr[k] * Ff + j];
    }
    if (tid < cnt) {
        int k = tid, n = snbr[k];
        const float* pp = pos + ((size_t)b * Nn + n) * 3;
        const float* qq = g_qpos + (size_t)bm * 3;
        featT[64 * FT_STRIDE + k] = pp[0] - qq[0];
        featT[65 * FT_STRIDE + k] = pp[1] - qq[1];
        featT[66 * FT_STRIDE + k] = pp[2] - qq[2];
    }
    __syncthreads();

    const int c = tid & 63, grp = tid >> 6;
    const int k0 = grp * 16;
    float ssum = 0.f, ssq = 0.f;
    if (k0 < cnt) {
        float acc[16];
        float bias = b1[c];
        #pragma unroll
        for (int kk = 0; kk < 16; kk++) acc[kk] = bias;
        #pragma unroll 4
        for (int j = 0; j < C0c; j++) {
            float w = W1s[j * C1c + c];
            const float4* fr = (const float4*)(featT + j * FT_STRIDE + k0);
            float4 f0 = fr[0], f1 = fr[1], f2 = fr[2], f3 = fr[3];
            acc[0]  += f0.x * w; acc[1]  += f0.y * w; acc[2]  += f0.z * w; acc[3]  += f0.w * w;
            acc[4]  += f1.x * w; acc[5]  += f1.y * w; acc[6]  += f1.z * w; acc[7]  += f1.w * w;
            acc[8]  += f2.x * w; acc[9]  += f2.y * w; acc[10] += f2.z * w; acc[11] += f2.w * w;
            acc[12] += f3.x * w; acc[13] += f3.y * w; acc[14] += f3.z * w; acc[15] += f3.w * w;
        }
        float* outp = g_h1 + (size_t)bm * (Kk * C1c);
        #pragma unroll
        for (int kk = 0; kk < 16; kk++) {
            int k = k0 + kk;
            if (k < cnt) {
                float h = fmaxf(acc[kk], 0.f);
                outp[k * C1c + c] = h;
                ssum += h; ssq += h * h;
            }
        }
    }
    red[grp * 64 + c] = ssum;
    red[256 + grp * 64 + c] = ssq;
    __syncthreads();
    if (grp == 0) {
        float s = red[c] + red[64 + c] + red[128 + c] + red[192 + c];
        float q = red[256 + c] + red[320 + c] + red[384 + c] + red[448 + c];
        g_ps1[(size_t)bm * C1c + c] = s;
        g_pq1[(size_t)bm * C1c + c] = q;
    }
}

// ---------------- BN stat reduction (deterministic, double) ----------------
template <int C>
__global__ void __launch_bounds__(256) k_bnstat(const float* __restrict__ gamma,
                                                const float* __restrict__ beta) {
    const float* ps = (C == C1c) ? g_ps1 : g_ps2;
    const float* pq = (C == C1c) ? g_pq1 : g_pq2;
    float* a = (C == C1c) ? g_a1 : g_a2;
    float* o = (C == C1c) ? g_o1 : g_o2;
    const int c = blockIdx.x, tid = threadIdx.x;
    __shared__ double ss[256], sq[256];
    double s = 0.0, q = 0.0;
    for (int i = tid; i < BM; i += 256) {
        s += (double)ps[(size_t)i * C + c];
        q += (double)pq[(size_t)i * C + c];
    }
    ss[tid] = s; sq[tid] = q; __syncthreads();
    for (int st = 128; st; st >>= 1) {
        if (tid < st) { ss[tid] += ss[tid + st]; sq[tid] += sq[tid + st]; }
        __syncthreads();
    }
    if (tid == 0) {
        double V = (double)g_V;
        double mean = ss[0] / V;
        double var = sq[0] / V - mean * mean;
        float af = gamma[c] * rsqrtf((float)var + 1e-5f);
        a[c] = af;
        o[c] = beta[c] - (float)mean * af;
    }
}

// ---------------- K5: BN1-apply + layer-2 (64->128) + BN2 stats + pooled extremes ----------
// 512 thr: c = tid&127, grp = tid>>7 (16 edges each).
// h2 is never materialized: we reduce masked {sum, sumsq, max, min} per (bm,c).
__global__ void __launch_bounds__(512) k_layer2(const float* __restrict__ W2,
                                                const float* __restrict__ b2) {
    extern __shared__ float smem[];
    float* h1ns = smem;                         // [64][68]
    float* W2s  = h1ns + C1c * FT_STRIDE;       // [64][128]
    float* red  = W2s + C1c * C2c;              // [4][4][128] (sum,sq,max,min)

    const int bm = blockIdx.x;
    const int tid = threadIdx.x;
    const int cnt = g_cnt[bm];

    for (int e = tid; e < C1c * C2c; e += 512) W2s[e] = W2[e];
    const float* h1p = g_h1 + (size_t)bm * (Kk * C1c);
    for (int e = tid; e < cnt * C1c; e += 512) {
        int k = e >> 6, j = e & 63;
        float v = h1p[k * C1c + j];
        h1ns[j * FT_STRIDE + k] = v * g_a1[j] + g_o1[j];
    }
    __syncthreads();

    const int c = tid & 127, grp = tid >> 7;
    const int k0 = grp * 16;
    float ssum = 0.f, ssq = 0.f, smx = -INFINITY, smn = INFINITY;
    if (k0 < cnt) {
        float acc[16];
        float bias = b2[c];
        #pragma unroll
        for (int kk = 0; kk < 16; kk++) acc[kk] = bias;
        #pragma unroll 4
        for (int j = 0; j < C1c; j++) {
            float w = W2s[j * C2c + c];
            const float4* fr = (const float4*)(h1ns + j * FT_STRIDE + k0);
            float4 f0 = fr[0], f1 = fr[1], f2 = fr[2], f3 = fr[3];
            acc[0]  += f0.x * w; acc[1]  += f0.y * w; acc[2]  += f0.z * w; acc[3]  += f0.w * w;
            acc[4]  += f1.x * w; acc[5]  += f1.y * w; acc[6]  += f1.z * w; acc[7]  += f1.w * w;
            acc[8]  += f2.x * w; acc[9]  += f2.y * w; acc[10] += f2.z * w; acc[11] += f2.w * w;
            acc[12] += f3.x * w; acc[13] += f3.y * w; acc[14] += f3.z * w; acc[15] += f3.w * w;
        }
        #pragma unroll
        for (int kk = 0; kk < 16; kk++) {
            int k = k0 + kk;
            if (k < cnt) {
                float h = fmaxf(acc[kk], 0.f);
                ssum += h; ssq += h * h;
                smx = fmaxf(smx, h); smn = fminf(smn, h);
            }
        }
    }
    red[          grp * 128 + c] = ssum;
    red[ 512 +    grp * 128 + c] = ssq;
    red[1024 +    grp * 128 + c] = smx;
    red[1536 +    grp * 128 + c] = smn;
    __syncthreads();
    if (grp == 0) {
        float s  = red[c]        + red[128 + c]  + red[256 + c]  + red[384 + c];
        float q  = red[512 + c]  + red[640 + c]  + red[768 + c]  + red[896 + c];
        float mx = fmaxf(fmaxf(red[1024 + c], red[1152 + c]),
                         fmaxf(red[1280 + c], red[1408 + c]));
        float mn = fminf(fminf(red[1536 + c], red[1664 + c]),
                         fminf(red[1792 + c], red[1920 + c]));
        g_ps2[(size_t)bm * C2c + c] = s;
        g_pq2[(size_t)bm * C2c + c] = q;
        g_hmax[(size_t)bm * C2c + c] = mx;
        g_hmin[(size_t)bm * C2c + c] = mn;
    }
}

// ---------------- K7: pooled BN2-apply ----------------
// max_k(a*h+o) == a*max_k(h)+o for a>=0, a*min_k(h)+o for a<0 (monotone fp ops,
// bitwise identical to the reference's elementwise-then-max). cnt>=1 always
// (the center itself is in-ball), so extremes are finite.
__global__ void __launch_bounds__(128) k_pool(float* __restrict__ out) {
    const int bm = blockIdx.x;
    const int c = threadIdx.x;
    const float a = g_a2[c], o = g_o2[c];
    const float h = (a >= 0.f) ? g_hmax[(size_t)bm * C2c + c]
                               : g_hmin[(size_t)bm * C2c + c];
    out[(size_t)bm * C2c + c] = a * h + o;
}

// ---------------- meta outputs: pos_out, batch_out, idx_glob ----------------
__global__ void __launch_bounds__(256) k_meta(float* __restrict__ out) {
    int i = blockIdx.x * blockDim.x + threadIdx.x;
    if (i >= BM) return;
    int b = i >> 10;
    out[OFF_POS + i * 3 + 0] = g_qpos[i * 3 + 0];
    out[OFF_POS + i * 3 + 1] = g_qpos[i * 3 + 1];
    out[OFF_POS + i * 3 + 2] = g_qpos[i * 3 + 2];
    out[OFF_BATCH + i] = (float)b;
    out[OFF_IDX + i] = (float)(g_idxLoc[i] + b * Nn);
}

// ---------------- host launcher ----------------
extern "C" void kernel_launch(void* const* d_in, const int* in_sizes, int n_in,
                              void* d_out, int out_size) {
    const float* x   = (const float*)d_in[0];
    const float* pos = (const float*)d_in[1];
    // d_in[2] = batch (unused; recomputed analytically)
    const float* W1  = (const float*)d_in[3];
    const float* b1  = (const float*)d_in[4];
    const float* g1  = (const float*)d_in[5];
    const float* be1 = (const float*)d_in[6];
    const float* W2  = (const float*)d_in[7];
    const float* b2  = (const float*)d_in[8];
    const float* g2  = (const float*)d_in[9];
    const float* be2 = (const float*)d_in[10];
    float* out = (float*)d_out;

    const int smem1 = (C0c * FT_STRIDE + C0c * C1c + 512) * (int)sizeof(float);
    const int smem2 = (C1c * FT_STRIDE + C1c * C2c + 2048) * (int)sizeof(float);
    cudaFuncSetAttribute(k_layer2, cudaFuncAttributeMaxDynamicSharedMemorySize, smem2);

    k_fps<<<Bb, 1024>>>(pos);
    k_ball<<<BM * 32 / 256, 256>>>(pos);
    k_count<<<1, 256>>>();
    k_meta<<<(BM + 255) / 256, 256>>>(out);
    k_layer1<<<BM, 256, smem1>>>(x, pos, W1, b1);
    k_bnstat<C1c><<<C1c, 256>>>(g1, be1);
    k_layer2<<<BM, 512, smem2>>>(W2, b2);
    k_bnstat<C2c><<<C2c, 256>>>(g2, be2);
    k_pool<<<BM, 128>>>(out);
}

// round 6
// speedup vs baseline: 1.1344x; 1.1344x over previous
#include <cuda_runtime.h>
#include <math.h>
#include <stdint.h>

// Problem constants
#define Bb   8
#define Nn   2048
#define Mm   1024
#define BM   8192          // B*M
#define Kk   64
#define Ff   64
#define C0c  67
#define C1c  64
#define C2c  128

// Output layout (float32, concatenated reference outputs)
#define OFF_POS   1048576   // BM*C2
#define OFF_BATCH 1073152   // + BM*3
#define OFF_IDX   1081344   // + BM

// ---------------- device scratch (static, no allocation) ----------------
__device__ int   g_idxLoc[BM];
__device__ float g_qpos[BM * 3];
__device__ int   g_nbr[BM * Kk];
__device__ int   g_cnt[BM];
__device__ int   g_V;
__device__ float g_h1[BM * Kk * C1c];           // 128 MB (layer-1 activations)
__device__ float g_hmax[BM * C2c];              // masked max of h2 (pre-BN)
__device__ float g_hmin[BM * C2c];              // masked min of h2 (pre-BN)
__device__ float g_ps1[BM * C1c], g_pq1[BM * C1c];
__device__ float g_ps2[BM * C2c], g_pq2[BM * C2c];
__device__ float g_a1[C1c], g_o1[C1c], g_a2[C2c], g_o2[C2c];

// Strict (non-contracted) squared distance — must match XLA's fp32 mul/add
__device__ __forceinline__ float dist2s(float ax, float ay, float az,
                                        float bx, float by, float bz) {
    float dx = ax - bx, dy = ay - by, dz = az - bz;
    return __fadd_rn(__fadd_rn(__fmul_rn(dx, dx), __fmul_rn(dy, dy)),
                     __fmul_rn(dz, dz));
}

// Packed fp32x2 FMA (Blackwell sm_100+; per-lane .rn — bitwise == scalar fmaf)
#define FMA_F32X2(d, a, b, c) \
    asm("fma.rn.f32x2 %0, %1, %2, %3;" : "=l"(d) : "l"(a), "l"(b), "l"(c))
#define PACK2(d, v) \
    asm("mov.b64 %0, {%1, %1};" : "=l"(d) : "r"(__float_as_uint(v)))
#define UNPACK2(lo, hi, p) do {                                              \
    unsigned _ulo, _uhi;                                                     \
    asm("mov.b64 {%0, %1}, %2;" : "=r"(_ulo), "=r"(_uhi) : "l"(p));          \
    lo = __uint_as_float(_ulo); hi = __uint_as_float(_uhi);                  \
} while (0)

// ---------------- K1: farthest point sampling (1 block / batch) ----------------
// Triple-buffered shared argmax slot (race-free with one barrier/iter).
// Warp argmax via redux.sync: max on distance bits, then min on tying index —
// same tie rule (max value, lowest index) as the packed-u64 shfl version.
__global__ void __launch_bounds__(1024) k_fps(const float* __restrict__ pos) {
    const int b = blockIdx.x;
    const int tid = threadIdx.x;
    __shared__ float sx[Nn], sy[Nn], sz[Nn];
    __shared__ unsigned long long skey[3];

    const float* p = pos + (size_t)b * Nn * 3;
    for (int e = tid; e < Nn * 3; e += 1024) {
        float v = p[e];
        int i = e / 3, c = e - 3 * i;
        if (c == 0) sx[i] = v; else if (c == 1) sy[i] = v; else sz[i] = v;
    }
    if (tid < 3) skey[tid] = 0ull;
    __syncthreads();

    const int i0 = tid, i1 = tid + 1024;
    const float x0 = sx[i0], y0 = sy[i0], z0 = sz[i0];
    const float x1 = sx[i1], y1 = sy[i1], z1 = sz[i1];

    float cx = sx[0], cy = sy[0], cz = sz[0];
    float m0 = dist2s(x0, y0, z0, cx, cy, cz);
    float m1 = dist2s(x1, y1, z1, cx, cy, cz);

    if (tid == 0) {
        g_idxLoc[b * Mm] = 0;
        float* qp = g_qpos + (size_t)(b * Mm) * 3;
        qp[0] = cx; qp[1] = cy; qp[2] = cz;
    }
    const int lane = tid & 31;

    for (int t = 1; t < Mm; ++t) {
        // local best of this thread's two points (ties -> lower index)
        float bv; int bi;
        if (m0 >= m1) { bv = m0; bi = i0; } else { bv = m1; bi = i1; }
        // warp argmax: distances >= 0 so float bits are monotone as u32
        unsigned vb = __float_as_uint(bv);
        unsigned rv;
        asm("redux.sync.max.u32 %0, %1, 0xffffffff;" : "=r"(rv) : "r"(vb));
        unsigned cand = (vb == rv) ? (unsigned)bi : 0xffffffffu;
        unsigned ri;
        asm("redux.sync.min.u32 %0, %1, 0xffffffff;" : "=r"(ri) : "r"(cand));
        const int slot = t % 3;
        if (lane == 0) {
            unsigned long long key =
                ((unsigned long long)rv << 32) | (unsigned)(Nn - (int)ri);
            atomicMax(&skey[slot], key);
        }
        __syncthreads();
        unsigned long long best = skey[slot];
        if (tid == 0) skey[(t + 2) % 3] = 0ull;   // read 2 epochs ago, written next epoch
        int nxt = Nn - (int)(unsigned int)(best & 0xffffffffu);
        cx = sx[nxt]; cy = sy[nxt]; cz = sz[nxt];
        if (tid == 0) {
            g_idxLoc[b * Mm + t] = nxt;
            float* qp = g_qpos + (size_t)(b * Mm + t) * 3;
            qp[0] = cx; qp[1] = cy; qp[2] = cz;
        }
        float d0 = dist2s(x0, y0, z0, cx, cy, cz);
        float d1 = dist2s(x1, y1, z1, cx, cy, cz);
        m0 = fminf(m0, d0);
        m1 = fminf(m1, d1);
    }
}

// ---------------- K2: ball query, first K in index order (1 warp / center) ----------------
__global__ void __launch_bounds__(256) k_ball(const float* __restrict__ pos) {
    int gw = (blockIdx.x * blockDim.x + threadIdx.x) >> 5;
    if (gw >= BM) return;
    const int lane = threadIdx.x & 31;
    const int b = gw >> 10;
    const float* p = pos + (size_t)b * Nn * 3;
    const float qx = g_qpos[gw * 3 + 0];
    const float qy = g_qpos[gw * 3 + 1];
    const float qz = g_qpos[gw * 3 + 2];
    int cnt = 0;
    for (int base = 0; base < Nn; base += 32) {
        int i = base + lane;
        float px = p[i * 3 + 0], py = p[i * 3 + 1], pz = p[i * 3 + 2];
        float d2 = dist2s(px, py, pz, qx, qy, qz);
        bool in = (d2 <= 0.04f);   // float32(R*R), same promotion as reference
        unsigned mask = __ballot_sync(0xffffffffu, in);
        int pre = __popc(mask & ((1u << lane) - 1u));
        int pp2 = cnt + pre;
        if (in && pp2 < Kk) g_nbr[gw * Kk + pp2] = i;
        cnt += __popc(mask);
        if (cnt >= Kk) break;
    }
    if (lane == 0) g_cnt[gw] = (cnt < Kk) ? cnt : Kk;
}

// ---------------- count total valid edges ----------------
__global__ void __launch_bounds__(256) k_count() {
    __shared__ int sr[256];
    int tid = threadIdx.x;
    int s = 0;
    for (int i = tid; i < BM; i += 256) s += g_cnt[i];
    sr[tid] = s; __syncthreads();
    for (int st = 128; st; st >>= 1) {
        if (tid < st) sr[tid] += sr[tid + st];
        __syncthreads();
    }
    if (tid == 0) g_V = sr[0];
}

// ---------------- K3: layer-1 (67->64) + partial BN1 stats ----------------
// block = one (b,m) center; 256 thr: c = tid&63 (channel), grp = tid>>6 (16 edges each)
// Inner product uses packed fma.rn.f32x2: 8 FFMA2 per j instead of 16 FFMA.
#define FT_STRIDE 68
__global__ void __launch_bounds__(256) k_layer1(
    const float* __restrict__ x, const float* __restrict__ pos,
    const float* __restrict__ W1, const float* __restrict__ b1) {
    extern __shared__ float smem[];
    float* featT = smem;                        // [67][68]
    float* W1s   = featT + C0c * FT_STRIDE;     // [67][64]
    float* red   = W1s + C0c * C1c;             // [2][4][64]
    __shared__ int snbr[Kk];

    const int bm = blockIdx.x;
    const int b = bm >> 10;
    const int tid = threadIdx.x;
    const int cnt = g_cnt[bm];

    if (tid < Kk) snbr[tid] = (tid < cnt) ? g_nbr[bm * Kk + tid] : 0;
    for (int e = tid; e < C0c * C1c; e += 256) W1s[e] = W1[e];
    __syncthreads();

    const float* xb = x + (size_t)b * Nn * Ff;
    for (int e = tid; e < cnt * Ff; e += 256) {
        int k = e >> 6, j = e & 63;
        featT[j * FT_STRIDE + k] = xb[(size_t)snbr[k] * Ff + j];
    }
    if (tid < cnt) {
        int k = tid, n = snbr[k];
        const float* pp = pos + ((size_t)b * Nn + n) * 3;
        const float* qq = g_qpos + (size_t)bm * 3;
        featT[64 * FT_STRIDE + k] = pp[0] - qq[0];
        featT[65 * FT_STRIDE + k] = pp[1] - qq[1];
        featT[66 * FT_STRIDE + k] = pp[2] - qq[2];
    }
    __syncthreads();

    const int c = tid & 63, grp = tid >> 6;
    const int k0 = grp * 16;
    float ssum = 0.f, ssq = 0.f;
    if (k0 < cnt) {
        unsigned long long acc[8];
        unsigned long long bb; PACK2(bb, b1[c]);
        #pragma unroll
        for (int i = 0; i < 8; i++) acc[i] = bb;
        #pragma unroll 4
        for (int j = 0; j < C0c; j++) {
            unsigned long long ww; PACK2(ww, W1s[j * C1c + c]);
            const ulonglong2* fr = (const ulonglong2*)(featT + j * FT_STRIDE + k0);
            ulonglong2 u0 = fr[0], u1 = fr[1], u2 = fr[2], u3 = fr[3];
            FMA_F32X2(acc[0], u0.x, ww, acc[0]);
            FMA_F32X2(acc[1], u0.y, ww, acc[1]);
            FMA_F32X2(acc[2], u1.x, ww, acc[2]);
            FMA_F32X2(acc[3], u1.y, ww, acc[3]);
            FMA_F32X2(acc[4], u2.x, ww, acc[4]);
            FMA_F32X2(acc[5], u2.y, ww, acc[5]);
            FMA_F32X2(acc[6], u3.x, ww, acc[6]);
            FMA_F32X2(acc[7], u3.y, ww, acc[7]);
        }
        float av[16];
        #pragma unroll
        for (int i = 0; i < 8; i++) UNPACK2(av[2 * i], av[2 * i + 1], acc[i]);
        float* outp = g_h1 + (size_t)bm * (Kk * C1c);
        #pragma unroll
        for (int kk = 0; kk < 16; kk++) {
            int k = k0 + kk;
            if (k < cnt) {
                float h = fmaxf(av[kk], 0.f);
                outp[k * C1c + c] = h;
                ssum += h; ssq += h * h;
            }
        }
    }
    red[grp * 64 + c] = ssum;
    red[256 + grp * 64 + c] = ssq;
    __syncthreads();
    if (grp == 0) {
        float s = red[c] + red[64 + c] + red[128 + c] + red[192 + c];
        float q = red[256 + c] + red[320 + c] + red[384 + c] + red[448 + c];
        g_ps1[(size_t)bm * C1c + c] = s;
        g_pq1[(size_t)bm * C1c + c] = q;
    }
}

// ---------------- BN stat reduction (deterministic, double) ----------------
template <int C>
__global__ void __launch_bounds__(256) k_bnstat(const float* __restrict__ gamma,
                                                const float* __restrict__ beta) {
    const float* ps = (C == C1c) ? g_ps1 : g_ps2;
    const float* pq = (C == C1c) ? g_pq1 : g_pq2;
    float* a = (C == C1c) ? g_a1 : g_a2;
    float* o = (C == C1c) ? g_o1 : g_o2;
    const int c = blockIdx.x, tid = threadIdx.x;
    __shared__ double ss[256], sq[256];
    double s = 0.0, q = 0.0;
    for (int i = tid; i < BM; i += 256) {
        s += (double)ps[(size_t)i * C + c];
        q += (double)pq[(size_t)i * C + c];
    }
    ss[tid] = s; sq[tid] = q; __syncthreads();
    for (int st = 128; st; st >>= 1) {
        if (tid < st) { ss[tid] += ss[tid + st]; sq[tid] += sq[tid + st]; }
        __syncthreads();
    }
    if (tid == 0) {
        double V = (double)g_V;
        double mean = ss[0] / V;
        double var = sq[0] / V - mean * mean;
        float af = gamma[c] * rsqrtf((float)var + 1e-5f);
        a[c] = af;
        o[c] = beta[c] - (float)mean * af;
    }
}

// ---------------- K5: BN1-apply + layer-2 (64->128) + BN2 stats + pooled extremes ----------
// 512 thr: c = tid&127, grp = tid>>7 (16 edges each). h2 never materialized.
__global__ void __launch_bounds__(512) k_layer2(const float* __restrict__ W2,
                                                const float* __restrict__ b2) {
    extern __shared__ float smem[];
    float* h1ns = smem;                         // [64][68]
    float* W2s  = h1ns + C1c * FT_STRIDE;       // [64][128]
    float* red  = W2s + C1c * C2c;              // [4][4][128] (sum,sq,max,min)

    const int bm = blockIdx.x;
    const int tid = threadIdx.x;
    const int cnt = g_cnt[bm];

    for (int e = tid; e < C1c * C2c; e += 512) W2s[e] = W2[e];
    const float* h1p = g_h1 + (size_t)bm * (Kk * C1c);
    for (int e = tid; e < cnt * C1c; e += 512) {
        int k = e >> 6, j = e & 63;
        float v = h1p[k * C1c + j];
        h1ns[j * FT_STRIDE + k] = v * g_a1[j] + g_o1[j];
    }
    __syncthreads();

    const int c = tid & 127, grp = tid >> 7;
    const int k0 = grp * 16;
    float ssum = 0.f, ssq = 0.f, smx = -INFINITY, smn = INFINITY;
    if (k0 < cnt) {
        unsigned long long acc[8];
        unsigned long long bb; PACK2(bb, b2[c]);
        #pragma unroll
        for (int i = 0; i < 8; i++) acc[i] = bb;
        #pragma unroll 4
        for (int j = 0; j < C1c; j++) {
            unsigned long long ww; PACK2(ww, W2s[j * C2c + c]);
            const ulonglong2* fr = (const ulonglong2*)(h1ns + j * FT_STRIDE + k0);
            ulonglong2 u0 = fr[0], u1 = fr[1], u2 = fr[2], u3 = fr[3];
            FMA_F32X2(acc[0], u0.x, ww, acc[0]);
            FMA_F32X2(acc[1], u0.y, ww, acc[1]);
            FMA_F32X2(acc[2], u1.x, ww, acc[2]);
            FMA_F32X2(acc[3], u1.y, ww, acc[3]);
            FMA_F32X2(acc[4], u2.x, ww, acc[4]);
            FMA_F32X2(acc[5], u2.y, ww, acc[5]);
            FMA_F32X2(acc[6], u3.x, ww, acc[6]);
            FMA_F32X2(acc[7], u3.y, ww, acc[7]);
        }
        float av[16];
        #pragma unroll
        for (int i = 0; i < 8; i++) UNPACK2(av[2 * i], av[2 * i + 1], acc[i]);
        #pragma unroll
        for (int kk = 0; kk < 16; kk++) {
            int k = k0 + kk;
            if (k < cnt) {
                float h = fmaxf(av[kk], 0.f);
                ssum += h; ssq += h * h;
                smx = fmaxf(smx, h); smn = fminf(smn, h);
            }
        }
    }
    red[          grp * 128 + c] = ssum;
    red[ 512 +    grp * 128 + c] = ssq;
    red[1024 +    grp * 128 + c] = smx;
    red[1536 +    grp * 128 + c] = smn;
    __syncthreads();
    if (grp == 0) {
        float s  = red[c]        + red[128 + c]  + red[256 + c]  + red[384 + c];
        float q  = red[512 + c]  + red[640 + c]  + red[768 + c]  + red[896 + c];
        float mx = fmaxf(fmaxf(red[1024 + c], red[1152 + c]),
                         fmaxf(red[1280 + c], red[1408 + c]));
        float mn = fminf(fminf(red[1536 + c], red[1664 + c]),
                         fminf(red[1792 + c], red[1920 + c]));
        g_ps2[(size_t)bm * C2c + c] = s;
        g_pq2[(size_t)bm * C2c + c] = q;
        g_hmax[(size_t)bm * C2c + c] = mx;
        g_hmin[(size_t)bm * C2c + c] = mn;
    }
}

// ---------------- K7: pooled BN2-apply ----------------
// max_k(a*h+o) == a*max_k(h)+o for a>=0, a*min_k(h)+o for a<0 (monotone fp ops,
// bitwise identical to elementwise-then-max). cnt>=1 always (center in-ball).
__global__ void __launch_bounds__(128) k_pool(float* __restrict__ out) {
    const int bm = blockIdx.x;
    const int c = threadIdx.x;
    const float a = g_a2[c], o = g_o2[c];
    const float h = (a >= 0.f) ? g_hmax[(size_t)bm * C2c + c]
                               : g_hmin[(size_t)bm * C2c + c];
    out[(size_t)bm * C2c + c] = a * h + o;
}

// ---------------- meta outputs: pos_out, batch_out, idx_glob ----------------
__global__ void __launch_bounds__(256) k_meta(float* __restrict__ out) {
    int i = blockIdx.x * blockDim.x + threadIdx.x;
    if (i >= BM) return;
    int b = i >> 10;
    out[OFF_POS + i * 3 + 0] = g_qpos[i * 3 + 0];
    out[OFF_POS + i * 3 + 1] = g_qpos[i * 3 + 1];
    out[OFF_POS + i * 3 + 2] = g_qpos[i * 3 + 2];
    out[OFF_BATCH + i] = (float)b;
    out[OFF_IDX + i] = (float)(g_idxLoc[i] + b * Nn);
}

// ---------------- host launcher ----------------
extern "C" void kernel_launch(void* const* d_in, const int* in_sizes, int n_in,
                              void* d_out, int out_size) {
    const float* x   = (const float*)d_in[0];
    const float* pos = (const float*)d_in[1];
    // d_in[2] = batch (unused; recomputed analytically)
    const float* W1  = (const float*)d_in[3];
    const float* b1  = (const float*)d_in[4];
    const float* g1  = (const float*)d_in[5];
    const float* be1 = (const float*)d_in[6];
    const float* W2  = (const float*)d_in[7];
    const float* b2  = (const float*)d_in[8];
    const float* g2  = (const float*)d_in[9];
    const float* be2 = (const float*)d_in[10];
    float* out = (float*)d_out;

    const int smem1 = (C0c * FT_STRIDE + C0c * C1c + 512) * (int)sizeof(float);
    const int smem2 = (C1c * FT_STRIDE + C1c * C2c + 2048) * (int)sizeof(float);
    cudaFuncSetAttribute(k_layer2, cudaFuncAttributeMaxDynamicSharedMemorySize, smem2);

    // Heavy kernels placed early so the ncu capture window (-s 5 -c 1) lands on
    // k_layer1 / k_layer2 instead of a trivial launch.
    k_fps<<<Bb, 1024>>>(pos);
    k_ball<<<BM * 32 / 256, 256>>>(pos);
    k_count<<<1, 256>>>();
    k_layer1<<<BM, 256, smem1>>>(x, pos, W1, b1);
    k_bnstat<C1c><<<C1c, 256>>>(g1, be1);
    k_layer2<<<BM, 512, smem2>>>(W2, b2);
    k_bnstat<C2c><<<C2c, 256>>>(g2, be2);
    k_pool<<<BM, 128>>>(out);
    k_meta<<<(BM + 255) / 256, 256>>>(out);
}

// round 7
// speedup vs baseline: 1.1778x; 1.0383x over previous
#include <cuda_runtime.h>
#include <math.h>
#include <stdint.h>

// Problem constants
#define Bb   8
#define Nn   2048
#define Mm   1024
#define BM   8192          // B*M
#define Kk   64
#define Ff   64
#define C0c  67
#define C1c  64
#define C2c  128

// Output layout (float32, concatenated reference outputs)
#define OFF_POS   1048576   // BM*C2
#define OFF_BATCH 1073152   // + BM*3
#define OFF_IDX   1081344   // + BM

// ---------------- device scratch (static, no allocation) ----------------
__device__ int   g_idxLoc[BM];
__device__ float g_qpos[BM * 3];
__device__ int   g_nbr[BM * Kk];
__device__ int   g_cnt[BM];
__device__ int   g_V;
// h1 stored TRANSPOSED: [bm][c][k]  (c = channel 0..63, k = edge 0..63)
__device__ float g_h1[BM * Kk * C1c];           // 128 MB
__device__ float g_hmax[BM * C2c];              // masked max of h2 (pre-BN)
__device__ float g_hmin[BM * C2c];              // masked min of h2 (pre-BN)
__device__ float g_ps1[BM * C1c], g_pq1[BM * C1c];
__device__ float g_ps2[BM * C2c], g_pq2[BM * C2c];
__device__ float g_a1[C1c], g_o1[C1c], g_a2[C2c], g_o2[C2c];

// Strict (non-contracted) squared distance — must match XLA's fp32 mul/add
__device__ __forceinline__ float dist2s(float ax, float ay, float az,
                                        float bx, float by, float bz) {
    float dx = ax - bx, dy = ay - by, dz = az - bz;
    return __fadd_rn(__fadd_rn(__fmul_rn(dx, dx), __fmul_rn(dy, dy)),
                     __fmul_rn(dz, dz));
}

// Packed fp32x2 FMA (Blackwell sm_100+; per-lane .rn — bitwise == scalar fmaf)
#define FMA_F32X2(d, a, b, c) \
    asm("fma.rn.f32x2 %0, %1, %2, %3;" : "=l"(d) : "l"(a), "l"(b), "l"(c))
#define PACK2(d, v) \
    asm("mov.b64 %0, {%1, %1};" : "=l"(d) : "r"(__float_as_uint(v)))
#define UNPACK2(lo, hi, p) do {                                              \
    unsigned _ulo, _uhi;                                                     \
    asm("mov.b64 {%0, %1}, %2;" : "=r"(_ulo), "=r"(_uhi) : "l"(p));          \
    lo = __uint_as_float(_ulo); hi = __uint_as_float(_uhi);                  \
} while (0)

// ---------------- K1: farthest point sampling (1 block / batch) ----------------
// 512 threads, 4 points/thread (identical per-point arithmetic -> identical
// trajectory). Triple-buffered shared argmax slot; redux.sync warp argmax.
__global__ void __launch_bounds__(512) k_fps(const float* __restrict__ pos) {
    const int b = blockIdx.x;
    const int tid = threadIdx.x;
    __shared__ float sx[Nn], sy[Nn], sz[Nn];
    __shared__ unsigned long long skey[3];

    const float* p = pos + (size_t)b * Nn * 3;
    for (int e = tid; e < Nn * 3; e += 512) {
        float v = p[e];
        int i = e / 3, c = e - 3 * i;
        if (c == 0) sx[i] = v; else if (c == 1) sy[i] = v; else sz[i] = v;
    }
    if (tid < 3) skey[tid] = 0ull;
    __syncthreads();

    const int i0 = tid, i1 = tid + 512, i2 = tid + 1024, i3 = tid + 1536;
    const float x0 = sx[i0], y0 = sy[i0], z0 = sz[i0];
    const float x1 = sx[i1], y1 = sy[i1], z1 = sz[i1];
    const float x2 = sx[i2], y2 = sy[i2], z2 = sz[i2];
    const float x3 = sx[i3], y3 = sy[i3], z3 = sz[i3];

    float cx = sx[0], cy = sy[0], cz = sz[0];
    float m0 = dist2s(x0, y0, z0, cx, cy, cz);
    float m1 = dist2s(x1, y1, z1, cx, cy, cz);
    float m2 = dist2s(x2, y2, z2, cx, cy, cz);
    float m3 = dist2s(x3, y3, z3, cx, cy, cz);

    if (tid == 0) {
        g_idxLoc[b * Mm] = 0;
        float* qp = g_qpos + (size_t)(b * Mm) * 3;
        qp[0] = cx; qp[1] = cy; qp[2] = cz;
    }
    const int lane = tid & 31;

    for (int t = 1; t < Mm; ++t) {
        // local best of 4 (ties -> lower index; index order i0<i1<i2<i3)
        float va; int ia;
        if (m0 >= m1) { va = m0; ia = i0; } else { va = m1; ia = i1; }
        float vb; int ib;
        if (m2 >= m3) { vb = m2; ib = i2; } else { vb = m3; ib = i3; }
        float bv; int bi;
        if (va >= vb) { bv = va; bi = ia; } else { bv = vb; bi = ib; }
        // warp argmax: distances >= 0 so float bits are monotone as u32
        unsigned vbits = __float_as_uint(bv);
        unsigned rv;
        asm("redux.sync.max.u32 %0, %1, 0xffffffff;" : "=r"(rv) : "r"(vbits));
        unsigned cand = (vbits == rv) ? (unsigned)bi : 0xffffffffu;
        unsigned ri;
        asm("redux.sync.min.u32 %0, %1, 0xffffffff;" : "=r"(ri) : "r"(cand));
        const int slot = t % 3;
        if (lane == 0) {
            unsigned long long key =
                ((unsigned long long)rv << 32) | (unsigned)(Nn - (int)ri);
            atomicMax(&skey[slot], key);
        }
        __syncthreads();
        unsigned long long best = skey[slot];
        if (tid == 0) skey[(t + 2) % 3] = 0ull;   // read 2 epochs ago, written next epoch
        int nxt = Nn - (int)(unsigned int)(best & 0xffffffffu);
        cx = sx[nxt]; cy = sy[nxt]; cz = sz[nxt];
        if (tid == 0) {
            g_idxLoc[b * Mm + t] = nxt;
            float* qp = g_qpos + (size_t)(b * Mm + t) * 3;
            qp[0] = cx; qp[1] = cy; qp[2] = cz;
        }
        m0 = fminf(m0, dist2s(x0, y0, z0, cx, cy, cz));
        m1 = fminf(m1, dist2s(x1, y1, z1, cx, cy, cz));
        m2 = fminf(m2, dist2s(x2, y2, z2, cx, cy, cz));
        m3 = fminf(m3, dist2s(x3, y3, z3, cx, cy, cz));
    }
}

// ---------------- K2: ball query, first K in index order (1 warp / center) ----------------
__global__ void __launch_bounds__(256) k_ball(const float* __restrict__ pos) {
    int gw = (blockIdx.x * blockDim.x + threadIdx.x) >> 5;
    if (gw >= BM) return;
    const int lane = threadIdx.x & 31;
    const int b = gw >> 10;
    const float* p = pos + (size_t)b * Nn * 3;
    const float qx = g_qpos[gw * 3 + 0];
    const float qy = g_qpos[gw * 3 + 1];
    const float qz = g_qpos[gw * 3 + 2];
    int cnt = 0;
    for (int base = 0; base < Nn; base += 32) {
        int i = base + lane;
        float px = p[i * 3 + 0], py = p[i * 3 + 1], pz = p[i * 3 + 2];
        float d2 = dist2s(px, py, pz, qx, qy, qz);
        bool in = (d2 <= 0.04f);   // float32(R*R), same promotion as reference
        unsigned mask = __ballot_sync(0xffffffffu, in);
        int pre = __popc(mask & ((1u << lane) - 1u));
        int pp2 = cnt + pre;
        if (in && pp2 < Kk) g_nbr[gw * Kk + pp2] = i;
        cnt += __popc(mask);
        if (cnt >= Kk) break;
    }
    if (lane == 0) g_cnt[gw] = (cnt < Kk) ? cnt : Kk;
}

// ---------------- count total valid edges ----------------
__global__ void __launch_bounds__(256) k_count() {
    __shared__ int sr[256];
    int tid = threadIdx.x;
    int s = 0;
    for (int i = tid; i < BM; i += 256) s += g_cnt[i];
    sr[tid] = s; __syncthreads();
    for (int st = 128; st; st >>= 1) {
        if (tid < st) sr[tid] += sr[tid + st];
        __syncthreads();
    }
    if (tid == 0) g_V = sr[0];
}

// ---------------- K3: layer-1 (67->64) + partial BN1 stats ----------------
// block = one (b,m) center; 256 thr; thread tile = 4 channels x 4 edges.
// eg = (tid&15)*4 (edge start), cg = (tid>>4)*4 (channel start).
// Per j: 1 LDS.128 features (2 natural f32x2 edge-pairs) + 1 LDS.128 weights
// (4 consecutive channels). Warp wavefronts/j: feat 256B coalesced (2) +
// weights 2x16B (1) = 3 (was 5).
#define FT_STRIDE 68
#define RED1_STR  68
__global__ void __launch_bounds__(256) k_layer1(
    const float* __restrict__ x, const float* __restrict__ pos,
    const float* __restrict__ W1, const float* __restrict__ b1) {
    extern __shared__ float smem[];
    float* featT = smem;                        // [67][68]
    float* W1s   = featT + C0c * FT_STRIDE;     // [67][64]
    float* redS  = W1s + C0c * C1c;             // [16][68]
    float* redQ  = redS + 16 * RED1_STR;        // [16][68]
    __shared__ int snbr[Kk];

    const int bm = blockIdx.x;
    const int b = bm >> 10;
    const int tid = threadIdx.x;
    const int cnt = g_cnt[bm];

    if (tid < Kk) snbr[tid] = (tid < cnt) ? g_nbr[bm * Kk + tid] : 0;
    for (int e = tid; e < C0c * C1c; e += 256) W1s[e] = W1[e];
    __syncthreads();

    const float* xb = x + (size_t)b * Nn * Ff;
    for (int e = tid; e < cnt * Ff; e += 256) {
        int k = e >> 6, j = e & 63;
        featT[j * FT_STRIDE + k] = xb[(size_t)snbr[k] * Ff + j];
    }
    if (tid < cnt) {
        int k = tid, n = snbr[k];
        const float* pp = pos + ((size_t)b * Nn + n) * 3;
        const float* qq = g_qpos + (size_t)bm * 3;
        featT[64 * FT_STRIDE + k] = pp[0] - qq[0];
        featT[65 * FT_STRIDE + k] = pp[1] - qq[1];
        featT[66 * FT_STRIDE + k] = pp[2] - qq[2];
    }
    __syncthreads();

    const int eg = (tid & 15) * 4;
    const int cg = (tid >> 4) * 4;
    float ps[4] = {0.f, 0.f, 0.f, 0.f};
    float pq[4] = {0.f, 0.f, 0.f, 0.f};
    if (eg < cnt) {
        unsigned long long acc[8];
        float4 b4 = *(const float4*)(b1 + cg);
        PACK2(acc[0], b4.x); acc[1] = acc[0];
        PACK2(acc[2], b4.y); acc[3] = acc[2];
        PACK2(acc[4], b4.z); acc[5] = acc[4];
        PACK2(acc[6], b4.w); acc[7] = acc[6];
        #pragma unroll 4
        for (int j = 0; j < C0c; j++) {
            float4 w4 = *(const float4*)(W1s + j * C1c + cg);
            ulonglong2 f = *(const ulonglong2*)(featT + j * FT_STRIDE + eg);
            unsigned long long w0, w1, w2, w3;
            PACK2(w0, w4.x); PACK2(w1, w4.y); PACK2(w2, w4.z); PACK2(w3, w4.w);
            FMA_F32X2(acc[0], f.x, w0, acc[0]);
            FMA_F32X2(acc[1], f.y, w0, acc[1]);
            FMA_F32X2(acc[2], f.x, w1, acc[2]);
            FMA_F32X2(acc[3], f.y, w1, acc[3]);
            FMA_F32X2(acc[4], f.x, w2, acc[4]);
            FMA_F32X2(acc[5], f.y, w2, acc[5]);
            FMA_F32X2(acc[6], f.x, w3, acc[6]);
            FMA_F32X2(acc[7], f.y, w3, acc[7]);
        }
        float* outb = g_h1 + (size_t)bm * (Kk * C1c);
        #pragma unroll
        for (int ch = 0; ch < 4; ch++) {
            float h0, h1, h2, h3;
            UNPACK2(h0, h1, acc[2 * ch]);
            UNPACK2(h2, h3, acc[2 * ch + 1]);
            h0 = fmaxf(h0, 0.f); h1 = fmaxf(h1, 0.f);
            h2 = fmaxf(h2, 0.f); h3 = fmaxf(h3, 0.f);
            // transposed, coalesced store: row = channel, col = edge
            *(float4*)(outb + (cg + ch) * Kk + eg) = make_float4(h0, h1, h2, h3);
            float hv[4] = {h0, h1, h2, h3};
            #pragma unroll
            for (int t = 0; t < 4; t++) {
                if (eg + t < cnt) { ps[ch] += hv[t]; pq[ch] += hv[t] * hv[t]; }
            }
        }
    }
    *(float4*)(redS + (tid & 15) * RED1_STR + cg) = make_float4(ps[0], ps[1], ps[2], ps[3]);
    *(float4*)(redQ + (tid & 15) * RED1_STR + cg) = make_float4(pq[0], pq[1], pq[2], pq[3]);
    __syncthreads();
    if (tid < C1c) {
        float s = 0.f, q = 0.f;
        #pragma unroll
        for (int g = 0; g < 16; g++) {
            s += redS[g * RED1_STR + tid];
            q += redQ[g * RED1_STR + tid];
        }
        g_ps1[(size_t)bm * C1c + tid] = s;
        g_pq1[(size_t)bm * C1c + tid] = q;
    }
}

// ---------------- BN stat reduction (deterministic, double) ----------------
template <int C>
__global__ void __launch_bounds__(256) k_bnstat(const float* __restrict__ gamma,
                                                const float* __restrict__ beta) {
    const float* ps = (C == C1c) ? g_ps1 : g_ps2;
    const float* pq = (C == C1c) ? g_pq1 : g_pq2;
    float* a = (C == C1c) ? g_a1 : g_a2;
    float* o = (C == C1c) ? g_o1 : g_o2;
    const int c = blockIdx.x, tid = threadIdx.x;
    __shared__ double ss[256], sq[256];
    double s = 0.0, q = 0.0;
    for (int i = tid; i < BM; i += 256) {
        s += (double)ps[(size_t)i * C + c];
        q += (double)pq[(size_t)i * C + c];
    }
    ss[tid] = s; sq[tid] = q; __syncthreads();
    for (int st = 128; st; st >>= 1) {
        if (tid < st) { ss[tid] += ss[tid + st]; sq[tid] += sq[tid + st]; }
        __syncthreads();
    }
    if (tid == 0) {
        double V = (double)g_V;
        double mean = ss[0] / V;
        double var = sq[0] / V - mean * mean;
        float af = gamma[c] * rsqrtf((float)var + 1e-5f);
        a[c] = af;
        o[c] = beta[c] - (float)mean * af;
    }
}

// ---------------- K5: BN1-apply + layer-2 (64->128) + BN2 stats + pooled extremes ----------
// 512 thr; thread tile = 4 channels x 4 edges. eg=(tid&15)*4, cg=(tid>>4)*4.
// h2 never materialized; g_h1 is transposed [c][k] so staging is coalesced and
// the smem transpose-store is conflict-free.
#define RED2_STR 132
__global__ void __launch_bounds__(512) k_layer2(const float* __restrict__ W2,
                                                const float* __restrict__ b2) {
    extern __shared__ float smem[];
    float* h1ns = smem;                         // [64][68]
    float* W2s  = h1ns + C1c * FT_STRIDE;       // [64][128]
    float* redA = W2s + C1c * C2c;              // [16][132]
    float* redB = redA + 16 * RED2_STR;         // [16][132]

    const int bm = blockIdx.x;
    const int tid = threadIdx.x;
    const int cnt = g_cnt[bm];

    // a1/o1 cached at the front of redA (free until after the main loop)
    float* a1s = redA;
    float* o1s = redA + C1c;
    if (tid < C1c) { a1s[tid] = g_a1[tid]; o1s[tid] = g_o1[tid]; }
    for (int e = tid; e < C1c * C2c; e += 512) W2s[e] = W2[e];
    __syncthreads();

    const float* h1p = g_h1 + (size_t)bm * (Kk * C1c);   // [j][k] layout
    for (int e = tid; e < C1c * Kk; e += 512) {
        int j = e >> 6, k = e & 63;
        h1ns[j * FT_STRIDE + k] = h1p[e] * a1s[j] + o1s[j];   // conflict-free STS
    }
    __syncthreads();

    const int eg = (tid & 15) * 4;
    const int cg = (tid >> 4) * 4;          // 0..124
    float ps[4] = {0.f, 0.f, 0.f, 0.f};
    float pq[4] = {0.f, 0.f, 0.f, 0.f};
    float pmx[4] = {-INFINITY, -INFINITY, -INFINITY, -INFINITY};
    float pmn[4] = { INFINITY,  INFINITY,  INFINITY,  INFINITY};
    if (eg < cnt) {
        unsigned long long acc[8];
        float4 b4 = *(const float4*)(b2 + cg);
        PACK2(acc[0], b4.x); acc[1] = acc[0];
        PACK2(acc[2], b4.y); acc[3] = acc[2];
        PACK2(acc[4], b4.z); acc[5] = acc[4];
        PACK2(acc[6], b4.w); acc[7] = acc[6];
        #pragma unroll 4
        for (int j = 0; j < C1c; j++) {
            float4 w4 = *(const float4*)(W2s + j * C2c + cg);
            ulonglong2 f = *(const ulonglong2*)(h1ns + j * FT_STRIDE + eg);
            unsigned long long w0, w1, w2, w3;
            PACK2(w0, w4.x); PACK2(w1, w4.y); PACK2(w2, w4.z); PACK2(w3, w4.w);
            FMA_F32X2(acc[0], f.x, w0, acc[0]);
            FMA_F32X2(acc[1], f.y, w0, acc[1]);
            FMA_F32X2(acc[2], f.x, w1, acc[2]);
            FMA_F32X2(acc[3], f.y, w1, acc[3]);
            FMA_F32X2(acc[4], f.x, w2, acc[4]);
            FMA_F32X2(acc[5], f.y, w2, acc[5]);
            FMA_F32X2(acc[6], f.x, w3, acc[6]);
            FMA_F32X2(acc[7], f.y, w3, acc[7]);
        }
        #pragma unroll
        for (int ch = 0; ch < 4; ch++) {
            float h0, h1, h2, h3;
            UNPACK2(h0, h1, acc[2 * ch]);
            UNPACK2(h2, h3, acc[2 * ch + 1]);
            float hv[4] = {fmaxf(h0, 0.f), fmaxf(h1, 0.f),
                           fmaxf(h2, 0.f), fmaxf(h3, 0.f)};
            #pragma unroll
            for (int t = 0; t < 4; t++) {
                if (eg + t < cnt) {
                    ps[ch] += hv[t]; pq[ch] += hv[t] * hv[t];
                    pmx[ch] = fmaxf(pmx[ch], hv[t]);
                    pmn[ch] = fminf(pmn[ch], hv[t]);
                }
            }
        }
    }
    // round 1: sum & sumsq
    __syncthreads();   // a1s/o1s reads are long done; make redA reuse safe
    *(float4*)(redA + (tid & 15) * RED2_STR + cg) = make_float4(ps[0], ps[1], ps[2], ps[3]);
    *(float4*)(redB + (tid & 15) * RED2_STR + cg) = make_float4(pq[0], pq[1], pq[2], pq[3]);
    __syncthreads();
    if (tid < C2c) {
        float s = 0.f, q = 0.f;
        #pragma unroll
        for (int g = 0; g < 16; g++) {
            s += redA[g * RED2_STR + tid];
            q += redB[g * RED2_STR + tid];
        }
        g_ps2[(size_t)bm * C2c + tid] = s;
        g_pq2[(size_t)bm * C2c + tid] = q;
    }
    __syncthreads();
    // round 2: max & min
    *(float4*)(redA + (tid & 15) * RED2_STR + cg) = make_float4(pmx[0], pmx[1], pmx[2], pmx[3]);
    *(float4*)(redB + (tid & 15) * RED2_STR + cg) = make_float4(pmn[0], pmn[1], pmn[2], pmn[3]);
    __syncthreads();
    if (tid < C2c) {
        float mx = -INFINITY, mn = INFINITY;
        #pragma unroll
        for (int g = 0; g < 16; g++) {
            mx = fmaxf(mx, redA[g * RED2_STR + tid]);
            mn = fminf(mn, redB[g * RED2_STR + tid]);
        }
        g_hmax[(size_t)bm * C2c + tid] = mx;
        g_hmin[(size_t)bm * C2c + tid] = mn;
    }
}

// ---------------- K7: pooled BN2-apply ----------------
// max_k(a*h+o) == a*max_k(h)+o for a>=0, a*min_k(h)+o for a<0 (monotone fp ops,
// bitwise identical to elementwise-then-max). cnt>=1 always (center in-ball).
__global__ void __launch_bounds__(128) k_pool(float* __restrict__ out) {
    const int bm = blockIdx.x;
    const int c = threadIdx.x;
    const float a = g_a2[c], o = g_o2[c];
    const float h = (a >= 0.f) ? g_hmax[(size_t)bm * C2c + c]
                               : g_hmin[(size_t)bm * C2c + c];
    out[(size_t)bm * C2c + c] = a * h + o;
}

// ---------------- meta outputs: pos_out, batch_out, idx_glob ----------------
__global__ void __launch_bounds__(256) k_meta(float* __restrict__ out) {
    int i = blockIdx.x * blockDim.x + threadIdx.x;
    if (i >= BM) return;
    int b = i >> 10;
    out[OFF_POS + i * 3 + 0] = g_qpos[i * 3 + 0];
    out[OFF_POS + i * 3 + 1] = g_qpos[i * 3 + 1];
    out[OFF_POS + i * 3 + 2] = g_qpos[i * 3 + 2];
    out[OFF_BATCH + i] = (float)b;
    out[OFF_IDX + i] = (float)(g_idxLoc[i] + b * Nn);
}

// ---------------- host launcher ----------------
extern "C" void kernel_launch(void* const* d_in, const int* in_sizes, int n_in,
                              void* d_out, int out_size) {
    const float* x   = (const float*)d_in[0];
    const float* pos = (const float*)d_in[1];
    // d_in[2] = batch (unused; recomputed analytically)
    const float* W1  = (const float*)d_in[3];
    const float* b1  = (const float*)d_in[4];
    const float* g1  = (const float*)d_in[5];
    const float* be1 = (const float*)d_in[6];
    const float* W2  = (const float*)d_in[7];
    const float* b2  = (const float*)d_in[8];
    const float* g2  = (const float*)d_in[9];
    const float* be2 = (const float*)d_in[10];
    float* out = (float*)d_out;

    const int smem1 = (C0c * FT_STRIDE + C0c * C1c + 2 * 16 * RED1_STR) * (int)sizeof(float);
    const int smem2 = (C1c * FT_STRIDE + C1c * C2c + 2 * 16 * RED2_STR) * (int)sizeof(float);
    cudaFuncSetAttribute(k_layer1, cudaFuncAttributeMaxDynamicSharedMemorySize, smem1);
    cudaFuncSetAttribute(k_layer2, cudaFuncAttributeMaxDynamicSharedMemorySize, smem2);

    // Heavy kernels early so the ncu capture window (-s 5 -c 1) lands on them.
    k_fps<<<Bb, 512>>>(pos);
    k_ball<<<BM * 32 / 256, 256>>>(pos);
    k_count<<<1, 256>>>();
    k_layer1<<<BM, 256, smem1>>>(x, pos, W1, b1);
    k_bnstat<C1c><<<C1c, 256>>>(g1, be1);
    k_layer2<<<BM, 512, smem2>>>(W2, b2);
    k_bnstat<C2c><<<C2c, 256>>>(g2, be2);
    k_pool<<<BM, 128>>>(out);
    k_meta<<<(BM + 255) / 256, 256>>>(out);
}